// round 7
// baseline (speedup 1.0000x reference)
#include <cuda_runtime.h>
#include <math.h>

#define TT 32
#define HH 16
#define HSS 32
#define EE 512
#define NT 256

// shared memory layout (in floats)
#define XS_OFF   0                       // xs[32][512]
#define QKV_OFF  (TT*EE)                 // qkv[3][32][33]
#define WEI_OFF  (QKV_OFF + 3*TT*33)     // wei[32][33]
#define OSM_OFF  (WEI_OFF + TT*33)       // osm[32][33]
#define WPT_OFF  (OSM_OFF + TT*33)       // wpT[32][516]
#define SMEM_FLOATS (WPT_OFF + TT*516)

__global__ void __launch_bounds__(NT, 1)
mha_fused_kernel(const float* __restrict__ x,
                 const float* __restrict__ Wq,
                 const float* __restrict__ Wk,
                 const float* __restrict__ Wv,
                 const float* __restrict__ Wp,
                 const float* __restrict__ bp,
                 float* __restrict__ out)
{
    extern __shared__ float sm[];
    float* xs  = sm + XS_OFF;
    float* qkv = sm + QKV_OFF;
    float* wei = sm + WEI_OFF;
    float* osm = sm + OSM_OFF;
    float* wpT = sm + WPT_OFF;

    const int b    = blockIdx.x;
    const int tid  = threadIdx.x;
    const int lane = tid & 31;
    const int warp = tid >> 5;

    // ---- load x[b] : [32][512] fp32 = 64KB, coalesced float4 ----
    {
        const float4* xg = (const float4*)(x + (size_t)b * TT * EE);
        float4* xs4 = (float4*)xs;
        #pragma unroll
        for (int i = 0; i < (TT*EE/4)/NT; i++)
            xs4[tid + i*NT] = xg[tid + i*NT];
    }

    // output accumulators: thread owns d = tid&31, e in [my_e0, my_e0+64)
    const int my_d  = tid & 31;
    const int my_e0 = (tid >> 5) * 64;
    float acc[64];
    #pragma unroll
    for (int j = 0; j < 64; j++) acc[j] = 0.f;

    __syncthreads();

    for (int h = 0; h < HH; h++) {
        // ---- stage wpT[c][e] = Wp[e][h*32+c]  (coalesced float4 reads, conflict-free STS)
        {
            for (int i = tid; i < EE*8; i += NT) {
                int e  = i >> 3;
                int c4 = i & 7;
                float4 v = ((const float4*)(Wp + (size_t)e * (HH*HSS) + h*32))[c4];
                wpT[(c4*4+0)*516 + e] = v.x;
                wpT[(c4*4+1)*516 + e] = v.y;
                wpT[(c4*4+2)*516 + e] = v.z;
                wpT[(c4*4+3)*516 + e] = v.w;
            }
        }

        // ---- QKV: combined [96 rows][512] x-dot. warp w owns rows w*12..w*12+11.
        // row r: m = r>>5 (q/k/v), d = r&31. Weight row cached in 16 regs/lane.
        for (int rr = 0; rr < 12; rr++) {
            int r = warp * 12 + rr;
            int m = r >> 5;
            int d = r & 31;
            const float* W = (m == 0 ? Wq : (m == 1 ? Wk : Wv))
                             + (size_t)(h * HSS + d) * EE;
            float wr[16];
            #pragma unroll
            for (int j = 0; j < 4; j++) {
                float4 w4 = *(const float4*)(W + j*128 + lane*4);
                wr[4*j+0] = w4.x; wr[4*j+1] = w4.y;
                wr[4*j+2] = w4.z; wr[4*j+3] = w4.w;
            }
            float* dst = qkv + m * TT * 33;
            for (int t = 0; t < TT; t++) {
                float s0 = 0.f, s1 = 0.f, s2 = 0.f, s3 = 0.f;
                #pragma unroll
                for (int j = 0; j < 4; j++) {
                    float4 xv = *(const float4*)(xs + t*EE + j*128 + lane*4);
                    if (j == 0) { s0 += wr[0]*xv.x;  s1 += wr[1]*xv.y;  s2 += wr[2]*xv.z;  s3 += wr[3]*xv.w; }
                    if (j == 1) { s0 += wr[4]*xv.x;  s1 += wr[5]*xv.y;  s2 += wr[6]*xv.z;  s3 += wr[7]*xv.w; }
                    if (j == 2) { s0 += wr[8]*xv.x;  s1 += wr[9]*xv.y;  s2 += wr[10]*xv.z; s3 += wr[11]*xv.w; }
                    if (j == 3) { s0 += wr[12]*xv.x; s1 += wr[13]*xv.y; s2 += wr[14]*xv.z; s3 += wr[15]*xv.w; }
                }
                float s = (s0 + s1) + (s2 + s3);
                #pragma unroll
                for (int o = 16; o; o >>= 1)
                    s += __shfl_xor_sync(0xffffffffu, s, o);
                if (lane == 0) dst[t*33 + d] = s;
            }
        }
        __syncthreads();

        // ---- wei = causal-masked softmax( Q K^T * 32^-0.5 )
        {
            int t  = tid >> 3;
            int s0 = (tid & 7) * 4;
            const float* Qr = qkv + t * 33;
            const float* Kb = qkv + TT * 33;
            float r[4];
            #pragma unroll
            for (int i = 0; i < 4; i++) {
                int s = s0 + i;
                const float* Kr = Kb + s * 33;
                float a0 = 0.f, a1 = 0.f;
                #pragma unroll
                for (int d = 0; d < 32; d += 2) {
                    a0 += Qr[d]   * Kr[d];
                    a1 += Qr[d+1] * Kr[d+1];
                }
                float a = a0 + a1;
                r[i] = (s <= t) ? a * 0.17677669529663689f : -3.0e38f;
            }
            float mx = fmaxf(fmaxf(r[0], r[1]), fmaxf(r[2], r[3]));
            #pragma unroll
            for (int o = 4; o; o >>= 1)
                mx = fmaxf(mx, __shfl_xor_sync(0xffffffffu, mx, o));
            float sum = 0.f;
            #pragma unroll
            for (int i = 0; i < 4; i++) { r[i] = __expf(r[i] - mx); sum += r[i]; }
            #pragma unroll
            for (int o = 4; o; o >>= 1)
                sum += __shfl_xor_sync(0xffffffffu, sum, o);
            float inv = 1.f / sum;
            #pragma unroll
            for (int i = 0; i < 4; i++) wei[t*33 + s0 + i] = r[i] * inv;
        }
        __syncthreads();

        // ---- O = wei @ V   [32][32]
        {
            int t  = tid >> 3;
            int d0 = (tid & 7) * 4;
            const float* Vb = qkv + 2 * TT * 33;
            const float* wr = wei + t * 33;
            float o0 = 0.f, o1 = 0.f, o2 = 0.f, o3 = 0.f;
            #pragma unroll
            for (int s = 0; s < 32; s++) {
                float w = wr[s];
                const float* Vr = Vb + s*33 + d0;
                o0 += w * Vr[0]; o1 += w * Vr[1];
                o2 += w * Vr[2]; o3 += w * Vr[3];
            }
            osm[t*33 + d0 + 0] = o0;
            osm[t*33 + d0 + 1] = o1;
            osm[t*33 + d0 + 2] = o2;
            osm[t*33 + d0 + 3] = o3;
        }
        __syncthreads();

        // ---- projection accumulate: acc[e] += sum_t O[t][my_d] * Wp[e][h*32+t]
        for (int t = 0; t < TT; t++) {
            float o = osm[t*33 + my_d];
            const float4* wp4 = (const float4*)(wpT + t*516 + my_e0);
            #pragma unroll
            for (int j4 = 0; j4 < 16; j4++) {
                float4 w = wp4[j4];
                acc[4*j4+0] += o * w.x;
                acc[4*j4+1] += o * w.y;
                acc[4*j4+2] += o * w.z;
                acc[4*j4+3] += o * w.w;
            }
        }
        __syncthreads();   // before next head overwrites qkv/wei/osm/wpT
    }

    // ---- write out[b][my_d][my_e0 .. my_e0+63] + bias
    {
        float* og = out + ((size_t)b * HSS + my_d) * EE + my_e0;
        #pragma unroll
        for (int j = 0; j < 64; j += 4) {
            float4 v;
            v.x = acc[j+0] + bp[my_e0 + j + 0];
            v.y = acc[j+1] + bp[my_e0 + j + 1];
            v.z = acc[j+2] + bp[my_e0 + j + 2];
            v.w = acc[j+3] + bp[my_e0 + j + 3];
            *(float4*)(og + j) = v;
        }
    }
}

extern "C" void kernel_launch(void* const* d_in, const int* in_sizes, int n_in,
                              void* d_out, int out_size)
{
    const float* x  = (const float*)d_in[0];
    const float* Wq = (const float*)d_in[1];
    const float* Wk = (const float*)d_in[2];
    const float* Wv = (const float*)d_in[3];
    const float* Wp = (const float*)d_in[4];
    const float* bp = (const float*)d_in[5];
    float* out = (float*)d_out;

    const int B = in_sizes[0] / (TT * EE);   // 4096
    const size_t smem_bytes = (size_t)SMEM_FLOATS * sizeof(float);

    cudaFuncSetAttribute(mha_fused_kernel,
                         cudaFuncAttributeMaxDynamicSharedMemorySize,
                         (int)smem_bytes);

    mha_fused_kernel<<<B, NT, smem_bytes>>>(x, Wq, Wk, Wv, Wp, bp, out);
}

// round 9
// speedup vs baseline: 5.8388x; 5.8388x over previous
#include <cuda_runtime.h>
#include <cstdint>
#include <cstddef>

#define BB   4096
#define TT   32
#define HH   16
#define HSS  32
#define EE   512
#define MTOT (BB*TT)

// ---------------------------------------------------------------------------
// Scratch: __device__ globals (sanctioned; no dynamic allocation anywhere)
// ---------------------------------------------------------------------------
__device__ float g_q [67108864];   // [B][H][T][D]
__device__ float g_k [67108864];
__device__ float g_v [67108864];
__device__ float g_ot[67108864];   // [b*32+d][h*32+t]  (K-major for proj GEMM)

// ---------------------------------------------------------------------------
// helpers
// ---------------------------------------------------------------------------
__device__ __forceinline__ uint32_t f2tf32(float f) {
    uint32_t r;
    asm("cvt.rna.tf32.f32 %0, %1;" : "=r"(r) : "f"(f));
    return r;
}

// m16n8k8 tf32 MMA, D += A*B (fp32 accumulate in place)
__device__ __forceinline__ void mma_tf32(float* c, const uint32_t* a, const uint32_t* b) {
    asm volatile(
        "mma.sync.aligned.m16n8k8.row.col.f32.tf32.tf32.f32 "
        "{%0,%1,%2,%3}, {%4,%5,%6,%7}, {%8,%9}, {%0,%1,%2,%3};"
        : "+f"(c[0]), "+f"(c[1]), "+f"(c[2]), "+f"(c[3])
        : "r"(a[0]), "r"(a[1]), "r"(a[2]), "r"(a[3]),
          "r"(b[0]), "r"(b[1]));
}

// ---------------------------------------------------------------------------
// GEMM tile machinery.
// CTA tile: 128(M) x 128(N), K stepped in chunks of 32.
// smem tile: [128 rows][36 cols] u32 (tf32 patterns), stride 36 => conflict-free
//   * MMA frag loads: bank = (4*quad + tq) % 32  -> 32 distinct banks
//   * STS.128 stores: per 8-lane phase banks 4*(r+c4) distinct
// Double-buffered: buf b at smu + b*18432 u32; within buf:
//   As_hi @0, As_lo @4608, Bs_hi @9216, Bs_lo @13824   (each 128*36=4608 u32)
// ---------------------------------------------------------------------------
#define TILE_U32   4608
#define BUF_U32    (4*TILE_U32)          // 18432
#define SMEM_GEMM  (2*BUF_U32*4)         // 147456 bytes

__device__ __forceinline__ void ldg_chunk(const float* __restrict__ gA,
                                          const float* __restrict__ gB,
                                          int tid, float4* pa, float4* pb) {
    #pragma unroll
    for (int t = 0; t < 4; t++) {
        int idx = tid + t * 256;
        int row = idx >> 3, c4 = idx & 7;
        pa[t] = *(const float4*)(gA + (size_t)row * EE + c4 * 4);
        pb[t] = *(const float4*)(gB + (size_t)row * EE + c4 * 4);
    }
}

__device__ __forceinline__ void split_store(uint32_t* hi, uint32_t* lo,
                                            int off, float4 v) {
    uint4 h, l;
    h.x = f2tf32(v.x); l.x = f2tf32(v.x - __uint_as_float(h.x));
    h.y = f2tf32(v.y); l.y = f2tf32(v.y - __uint_as_float(h.y));
    h.z = f2tf32(v.z); l.z = f2tf32(v.z - __uint_as_float(h.z));
    h.w = f2tf32(v.w); l.w = f2tf32(v.w - __uint_as_float(h.w));
    *(uint4*)(hi + off) = h;
    *(uint4*)(lo + off) = l;
}

__device__ __forceinline__ void sts_chunk(uint32_t* buf, int tid,
                                          const float4* pa, const float4* pb) {
    #pragma unroll
    for (int t = 0; t < 4; t++) {
        int idx = tid + t * 256;
        int row = idx >> 3, c4 = idx & 7;
        int off = row * 36 + c4 * 4;
        split_store(buf,              buf + TILE_U32,   off, pa[t]);
        split_store(buf + 2*TILE_U32, buf + 3*TILE_U32, off, pb[t]);
    }
}

__device__ __forceinline__ void compute_chunk(const uint32_t* __restrict__ buf,
                                              int wm, int wn, int quad, int tq,
                                              float acc[4][4][4]) {
    const uint32_t* As_hi = buf;
    const uint32_t* As_lo = buf + TILE_U32;
    const uint32_t* Bs_hi = buf + 2*TILE_U32;
    const uint32_t* Bs_lo = buf + 3*TILE_U32;
    #pragma unroll
    for (int ks = 0; ks < 4; ks++) {
        const int kk = ks * 8;
        uint32_t ah[4][4], al[4][4], bh[4][2], bl[4][2];
        #pragma unroll
        for (int mt = 0; mt < 4; mt++) {
            int r = (wm*64 + mt*16 + quad) * 36 + kk + tq;
            ah[mt][0] = As_hi[r];       ah[mt][1] = As_hi[r + 288];
            ah[mt][2] = As_hi[r + 4];   ah[mt][3] = As_hi[r + 292];
            al[mt][0] = As_lo[r];       al[mt][1] = As_lo[r + 288];
            al[mt][2] = As_lo[r + 4];   al[mt][3] = As_lo[r + 292];
        }
        #pragma unroll
        for (int nt = 0; nt < 4; nt++) {
            int rb = (wn*32 + nt*8 + quad) * 36 + kk + tq;
            bh[nt][0] = Bs_hi[rb];  bh[nt][1] = Bs_hi[rb + 4];
            bl[nt][0] = Bs_lo[rb];  bl[nt][1] = Bs_lo[rb + 4];
        }
        #pragma unroll
        for (int mt = 0; mt < 4; mt++)
            #pragma unroll
            for (int nt = 0; nt < 4; nt++) {
                mma_tf32(acc[mt][nt], ah[mt], bh[nt]);   // hi*hi
                mma_tf32(acc[mt][nt], al[mt], bh[nt]);   // lo*hi
                mma_tf32(acc[mt][nt], ah[mt], bl[nt]);   // hi*lo
            }
    }
}

// Shared GEMM mainloop: computes acc = A[128,512] @ B[128,512]^T for one tile
__device__ __forceinline__ void gemm_mainloop(const float* __restrict__ gA,
                                              const float* __restrict__ gB,
                                              uint32_t* smu, int tid,
                                              int wm, int wn, int quad, int tq,
                                              float acc[4][4][4]) {
    float4 pa[4], pb[4];
    ldg_chunk(gA, gB, tid, pa, pb);
    sts_chunk(smu, tid, pa, pb);
    __syncthreads();
    for (int ck = 0; ck < 16; ck++) {
        if (ck < 15)
            ldg_chunk(gA + (ck + 1) * 32, gB + (ck + 1) * 32, tid, pa, pb);
        compute_chunk(smu + (ck & 1) * BUF_U32, wm, wn, quad, tq, acc);
        __syncthreads();
        if (ck < 15) {
            sts_chunk(smu + ((ck + 1) & 1) * BUF_U32, tid, pa, pb);
            __syncthreads();
        }
    }
}

// ---------------------------------------------------------------------------
// Kernel 1: QKV projection. grid(12, 1024): x = weight tile (mat*4 + ntile),
// y = M tile. Weight-tile-fastest ordering keeps the x slice hot in L2.
// ---------------------------------------------------------------------------
__global__ void __launch_bounds__(256, 1)
gemm_qkv_kernel(const float* __restrict__ x,  const float* __restrict__ Wq,
                const float* __restrict__ Wk, const float* __restrict__ Wv)
{
    extern __shared__ uint32_t smu[];
    const int tid = threadIdx.x, warp = tid >> 5, lane = tid & 31;
    const int quad = lane >> 2, tq = lane & 3;
    const int wm = warp & 1, wn = warp >> 1;

    const int wti = blockIdx.x;           // 0..11
    const int mat = wti >> 2;
    const int n0  = (wti & 3) * 128;
    const int m0  = blockIdx.y * 128;

    const float* W  = (mat == 0) ? Wq : (mat == 1) ? Wk : Wv;
    float acc[4][4][4];
    #pragma unroll
    for (int i = 0; i < 4; i++)
        #pragma unroll
        for (int j = 0; j < 4; j++)
            #pragma unroll
            for (int k = 0; k < 4; k++) acc[i][j][k] = 0.f;

    gemm_mainloop(x + (size_t)m0 * EE, W + (size_t)n0 * EE,
                  smu, tid, wm, wn, quad, tq, acc);

    // epilogue -> g_{q,k,v}[b][h][t][d]
    float* gout = (mat == 0) ? g_q : (mat == 1) ? g_k : g_v;
    #pragma unroll
    for (int mt = 0; mt < 4; mt++) {
        #pragma unroll
        for (int nt = 0; nt < 4; nt++) {
            const int n = n0 + wn * 32 + nt * 8 + 2 * tq;   // within this mat
            const int h = n >> 5, d = n & 31;
            #pragma unroll
            for (int rr = 0; rr < 2; rr++) {
                const int m = m0 + wm * 64 + mt * 16 + quad + rr * 8;
                const int b = m >> 5, t = m & 31;
                float2 v = make_float2(acc[mt][nt][rr*2], acc[mt][nt][rr*2+1]);
                *(float2*)(gout + (((size_t)b * HH + h) * TT + t) * HSS + d) = v;
            }
        }
    }
}

// ---------------------------------------------------------------------------
// Kernel 2: attention. one warp per (b,h). Exact fp32 causal softmax.
// Writes g_ot[b*32+d][h*32+t] (the head-concat transpose, K-major for K3).
// ---------------------------------------------------------------------------
__global__ void __launch_bounds__(256, 1)
attn_kernel()
{
    extern __shared__ uint32_t smu[];
    float* smf = (float*)smu;
    const int tid = threadIdx.x, warp = tid >> 5, lane = tid & 31;
    const int g = blockIdx.x * 8 + warp;          // g = b*16 + h
    const int t = lane;
    float* ksm = smf + warp * 2304;               // 32 rows, stride 36
    float* vsm = ksm + 1152;

    const float* qb = g_q + (size_t)g * 1024;
    const float* kb = g_k + (size_t)g * 1024;
    const float* vb = g_v + (size_t)g * 1024;

    float q[32];
    #pragma unroll
    for (int j = 0; j < 8; j++) {
        float4 v = *(const float4*)(qb + t * 32 + j * 4);
        q[4*j] = v.x; q[4*j+1] = v.y; q[4*j+2] = v.z; q[4*j+3] = v.w;
        *(float4*)(ksm + t * 36 + j * 4) = *(const float4*)(kb + t * 32 + j * 4);
        *(float4*)(vsm + t * 36 + j * 4) = *(const float4*)(vb + t * 32 + j * 4);
    }
    __syncwarp();

    float r[32];
    #pragma unroll
    for (int s = 0; s < 32; s++) {
        float a = 0.f;
        #pragma unroll
        for (int j = 0; j < 8; j++) {
            float4 kv = *(const float4*)(ksm + s * 36 + j * 4);
            a += q[4*j]*kv.x + q[4*j+1]*kv.y + q[4*j+2]*kv.z + q[4*j+3]*kv.w;
        }
        r[s] = (s <= t) ? a * 0.17677669529663689f : -3.0e38f;
    }
    float mx = r[0];
    #pragma unroll
    for (int s = 1; s < 32; s++) mx = fmaxf(mx, r[s]);
    float sum = 0.f;
    #pragma unroll
    for (int s = 0; s < 32; s++) { r[s] = __expf(r[s] - mx); sum += r[s]; }
    const float inv = 1.f / sum;

    float o[32];
    #pragma unroll
    for (int j = 0; j < 32; j++) o[j] = 0.f;
    #pragma unroll
    for (int s = 0; s < 32; s++) {
        float w = r[s];
        #pragma unroll
        for (int j = 0; j < 8; j++) {
            float4 vv = *(const float4*)(vsm + s * 36 + j * 4);
            o[4*j] += w*vv.x; o[4*j+1] += w*vv.y; o[4*j+2] += w*vv.z; o[4*j+3] += w*vv.w;
        }
    }
    __syncwarp();   // done reading ksm -> reuse as transpose buffer
    #pragma unroll
    for (int j = 0; j < 32; j++) ksm[t * 33 + j] = o[j] * inv;
    __syncwarp();

    const int b = g >> 4, h = g & 15;
    float* dst = g_ot + ((size_t)b * 32 + lane) * EE + h * 32;   // lane = d
    #pragma unroll
    for (int tt = 0; tt < 32; tt += 4) {
        float4 v;
        v.x = ksm[(tt + 0) * 33 + lane];
        v.y = ksm[(tt + 1) * 33 + lane];
        v.z = ksm[(tt + 2) * 33 + lane];
        v.w = ksm[(tt + 3) * 33 + lane];
        *(float4*)(dst + tt) = v;
    }
}

// ---------------------------------------------------------------------------
// Kernel 3: output projection + bias. grid(4, 1024): x = N tile, y = M tile.
// out[m][n] = sum_c g_ot[m][c] * Wp[n][c] + bp[n]
// ---------------------------------------------------------------------------
__global__ void __launch_bounds__(256, 1)
gemm_proj_kernel(const float* __restrict__ Wp, const float* __restrict__ bp,
                 float* __restrict__ out)
{
    extern __shared__ uint32_t smu[];
    const int tid = threadIdx.x, warp = tid >> 5, lane = tid & 31;
    const int quad = lane >> 2, tq = lane & 3;
    const int wm = warp & 1, wn = warp >> 1;
    const int n0 = blockIdx.x * 128;
    const int m0 = blockIdx.y * 128;

    float acc[4][4][4];
    #pragma unroll
    for (int i = 0; i < 4; i++)
        #pragma unroll
        for (int j = 0; j < 4; j++)
            #pragma unroll
            for (int k = 0; k < 4; k++) acc[i][j][k] = 0.f;

    gemm_mainloop(g_ot + (size_t)m0 * EE, Wp + (size_t)n0 * EE,
                  smu, tid, wm, wn, quad, tq, acc);

    #pragma unroll
    for (int mt = 0; mt < 4; mt++) {
        #pragma unroll
        for (int nt = 0; nt < 4; nt++) {
            const int n = n0 + wn * 32 + nt * 8 + 2 * tq;
            const float b0 = bp[n], b1 = bp[n + 1];
            #pragma unroll
            for (int rr = 0; rr < 2; rr++) {
                const int m = m0 + wm * 64 + mt * 16 + quad + rr * 8;
                float2 v = make_float2(acc[mt][nt][rr*2] + b0,
                                       acc[mt][nt][rr*2+1] + b1);
                *(float2*)(out + (size_t)m * EE + n) = v;
            }
        }
    }
}

// ---------------------------------------------------------------------------
// Launch
// ---------------------------------------------------------------------------
extern "C" void kernel_launch(void* const* d_in, const int* in_sizes, int n_in,
                              void* d_out, int out_size)
{
    const float* x  = (const float*)d_in[0];
    const float* Wq = (const float*)d_in[1];
    const float* Wk = (const float*)d_in[2];
    const float* Wv = (const float*)d_in[3];
    const float* Wp = (const float*)d_in[4];
    const float* bp = (const float*)d_in[5];
    float* out = (float*)d_out;

    const int smem_attn = 8 * 2304 * 4;   // 73728

    cudaFuncSetAttribute(gemm_qkv_kernel,  cudaFuncAttributeMaxDynamicSharedMemorySize, SMEM_GEMM);
    cudaFuncSetAttribute(gemm_proj_kernel, cudaFuncAttributeMaxDynamicSharedMemorySize, SMEM_GEMM);
    cudaFuncSetAttribute(attn_kernel,      cudaFuncAttributeMaxDynamicSharedMemorySize, smem_attn);

    gemm_qkv_kernel<<<dim3(12, 1024), 256, SMEM_GEMM>>>(x, Wq, Wk, Wv);
    attn_kernel<<<(BB * HH) / 8, 256, smem_attn>>>();
    gemm_proj_kernel<<<dim3(4, 1024), 256, SMEM_GEMM>>>(Wp, bp, out);
}

// round 13
// speedup vs baseline: 7.8573x; 1.3457x over previous
#include <cuda_runtime.h>
#include <cuda_bf16.h>
#include <cstdint>
#include <cstddef>

#define BB   4096
#define TT   32
#define HH   16
#define HSS  32
#define EE   512
#define MTOT (BB*TT)

// ---------------------------------------------------------------------------
// Scratch: __device__ globals (sanctioned; no dynamic allocation anywhere)
// ---------------------------------------------------------------------------
__device__ float g_q [67108864];   // [B][H][T][D]
__device__ float g_k [67108864];
__device__ float g_v [67108864];
__device__ float g_ot[67108864];   // [b*32+d][h*32+t]  (K-major for proj GEMM)

// ---------------------------------------------------------------------------
// helpers
// ---------------------------------------------------------------------------
// split x into hi(bf16) + lo(bf16); pack two consecutive-k elements into b32
__device__ __forceinline__ void split2(float x, float y,
                                       uint32_t& hi, uint32_t& lo) {
    __nv_bfloat16 hx = __float2bfloat16(x);
    __nv_bfloat16 hy = __float2bfloat16(y);
    float rx = x - __bfloat162float(hx);
    float ry = y - __bfloat162float(hy);
    __nv_bfloat16 lx = __float2bfloat16(rx);
    __nv_bfloat16 ly = __float2bfloat16(ry);
    hi = ((uint32_t)__bfloat16_as_ushort(hy) << 16) | __bfloat16_as_ushort(hx);
    lo = ((uint32_t)__bfloat16_as_ushort(ly) << 16) | __bfloat16_as_ushort(lx);
}

// m16n8k16 bf16 MMA, D += A*B (fp32 accumulate in place)
__device__ __forceinline__ void mma_bf16(float* c, const uint32_t* a, const uint32_t* b) {
    asm volatile(
        "mma.sync.aligned.m16n8k16.row.col.f32.bf16.bf16.f32 "
        "{%0,%1,%2,%3}, {%4,%5,%6,%7}, {%8,%9}, {%0,%1,%2,%3};"
        : "+f"(c[0]), "+f"(c[1]), "+f"(c[2]), "+f"(c[3])
        : "r"(a[0]), "r"(a[1]), "r"(a[2]), "r"(a[3]),
          "r"(b[0]), "r"(b[1]));
}

// ---------------------------------------------------------------------------
// GEMM tile machinery.
// CTA tile 128x128, K chunks of 32. Tiles stored as bf16 pairs (b32), row
// stride 24 u32 (96B; stride%32==8 -> LDS.64 hits 32 distinct banks/phase).
// k-pair p mapped to slot s so pairs (tq, tq+4) sit adjacent -> one LDS.64
// yields (a0,a2) / (a1,a3) / (b0,b1).
//   slot(p): g=p>>3, q=p&7 -> g*8 + 2*(q&3) + (q>>2)
// Buffers: [As_hi | As_lo | Bs_hi | Bs_lo] each 128*24 u32; double buffered.
// ---------------------------------------------------------------------------
#define TILE_U32   3072                  // 128 * 24
#define BUF_U32    (4*TILE_U32)          // 12288
#define SMEM_GEMM  (2*BUF_U32*4)         // 98304 bytes

__device__ __forceinline__ void ldg_chunk(const float* __restrict__ gA,
                                          const float* __restrict__ gB,
                                          int tid, float4* pa, float4* pb) {
    #pragma unroll
    for (int t = 0; t < 4; t++) {
        int idx = tid + t * 256;
        int row = idx >> 3, c4 = idx & 7;
        pa[t] = *(const float4*)(gA + (size_t)row * EE + c4 * 4);
        pb[t] = *(const float4*)(gB + (size_t)row * EE + c4 * 4);
    }
}

__device__ __forceinline__ void sts_chunk(uint32_t* __restrict__ buf, int tid,
                                          const float4* pa, const float4* pb) {
    #pragma unroll
    for (int t = 0; t < 4; t++) {
        int idx = tid + t * 256;
        int row = idx >> 3, c4 = idx & 7;
        // slot for pair p=2*c4 :  g=(c4>>2), lut(c4&3)={0,4,1,5}; pair p+1 at +2
        int s0 = ((c4 >> 2) << 3) | ((c4 & 1) << 2) | ((c4 & 3) >> 1);
        int base = row * 24 + s0;
        uint32_t h0, l0, h1, l1;
        split2(pa[t].x, pa[t].y, h0, l0);
        split2(pa[t].z, pa[t].w, h1, l1);
        buf[base]                = h0;  buf[base + 2]                = h1;
        buf[TILE_U32 + base]     = l0;  buf[TILE_U32 + base + 2]     = l1;
        split2(pb[t].x, pb[t].y, h0, l0);
        split2(pb[t].z, pb[t].w, h1, l1);
        buf[2*TILE_U32 + base]     = h0;  buf[2*TILE_U32 + base + 2]     = h1;
        buf[3*TILE_U32 + base]     = l0;  buf[3*TILE_U32 + base + 2]     = l1;
    }
}

__device__ __forceinline__ void compute_chunk(const uint32_t* __restrict__ buf,
                                              int wm, int wn, int quad, int tq,
                                              float acc[4][4][4]) {
    const uint32_t* As_hi = buf;
    const uint32_t* As_lo = buf + TILE_U32;
    const uint32_t* Bs_hi = buf + 2*TILE_U32;
    const uint32_t* Bs_lo = buf + 3*TILE_U32;
    #pragma unroll
    for (int ks = 0; ks < 2; ks++) {
        const int col = ks * 8 + 2 * tq;
        uint32_t ah[4][4], al[4][4], bh[4][2], bl[4][2];
        #pragma unroll
        for (int mt = 0; mt < 4; mt++) {
            int r = (wm*64 + mt*16 + quad) * 24 + col;
            uint2 x0 = *(const uint2*)(As_hi + r);
            uint2 x1 = *(const uint2*)(As_hi + r + 8*24);
            ah[mt][0] = x0.x; ah[mt][1] = x1.x; ah[mt][2] = x0.y; ah[mt][3] = x1.y;
            uint2 y0 = *(const uint2*)(As_lo + r);
            uint2 y1 = *(const uint2*)(As_lo + r + 8*24);
            al[mt][0] = y0.x; al[mt][1] = y1.x; al[mt][2] = y0.y; al[mt][3] = y1.y;
        }
        #pragma unroll
        for (int nt = 0; nt < 4; nt++) {
            int rb = (wn*32 + nt*8 + quad) * 24 + col;
            uint2 b0 = *(const uint2*)(Bs_hi + rb);
            bh[nt][0] = b0.x; bh[nt][1] = b0.y;
            uint2 b1 = *(const uint2*)(Bs_lo + rb);
            bl[nt][0] = b1.x; bl[nt][1] = b1.y;
        }
        #pragma unroll
        for (int mt = 0; mt < 4; mt++)
            #pragma unroll
            for (int nt = 0; nt < 4; nt++) {
                mma_bf16(acc[mt][nt], ah[mt], bh[nt]);   // hi*hi
                mma_bf16(acc[mt][nt], al[mt], bh[nt]);   // lo*hi
                mma_bf16(acc[mt][nt], ah[mt], bl[nt]);   // hi*lo
            }
    }
}

// Mainloop: acc = A[128,512] @ B[128,512]^T, one __syncthreads per chunk.
__device__ __forceinline__ void gemm_mainloop(const float* __restrict__ gA,
                                              const float* __restrict__ gB,
                                              uint32_t* smu, int tid,
                                              int wm, int wn, int quad, int tq,
                                              float acc[4][4][4]) {
    float4 pa[4], pb[4];
    ldg_chunk(gA, gB, tid, pa, pb);
    sts_chunk(smu, tid, pa, pb);
    __syncthreads();
    for (int ck = 0; ck < 16; ck++) {
        if (ck < 15)
            ldg_chunk(gA + (ck + 1) * 32, gB + (ck + 1) * 32, tid, pa, pb);
        compute_chunk(smu + (ck & 1) * BUF_U32, wm, wn, quad, tq, acc);
        if (ck < 15)
            sts_chunk(smu + ((ck + 1) & 1) * BUF_U32, tid, pa, pb);
        __syncthreads();
    }
}

// ---------------------------------------------------------------------------
// Kernel 1: QKV projection. grid(12, 1024): x = weight tile (mat*4 + ntile),
// y = M tile. Weight-tile-fastest keeps the x slice hot in L2.
// ---------------------------------------------------------------------------
__global__ void __launch_bounds__(256, 1)
gemm_qkv_kernel(const float* __restrict__ x,  const float* __restrict__ Wq,
                const float* __restrict__ Wk, const float* __restrict__ Wv)
{
    extern __shared__ uint32_t smu[];
    const int tid = threadIdx.x, warp = tid >> 5, lane = tid & 31;
    const int quad = lane >> 2, tq = lane & 3;
    const int wm = warp & 1, wn = warp >> 1;

    const int wti = blockIdx.x;           // 0..11
    const int mat = wti >> 2;
    const int n0  = (wti & 3) * 128;
    const int m0  = blockIdx.y * 128;

    const float* W = (mat == 0) ? Wq : (mat == 1) ? Wk : Wv;
    float acc[4][4][4];
    #pragma unroll
    for (int i = 0; i < 4; i++)
        #pragma unroll
        for (int j = 0; j < 4; j++)
            #pragma unroll
            for (int k = 0; k < 4; k++) acc[i][j][k] = 0.f;

    gemm_mainloop(x + (size_t)m0 * EE, W + (size_t)n0 * EE,
                  smu, tid, wm, wn, quad, tq, acc);

    // epilogue -> g_{q,k,v}[b][h][t][d]
    float* gout = (mat == 0) ? g_q : (mat == 1) ? g_k : g_v;
    #pragma unroll
    for (int mt = 0; mt < 4; mt++) {
        #pragma unroll
        for (int nt = 0; nt < 4; nt++) {
            const int n = n0 + wn * 32 + nt * 8 + 2 * tq;
            const int h = n >> 5, d = n & 31;
            #pragma unroll
            for (int rr = 0; rr < 2; rr++) {
                const int m = m0 + wm * 64 + mt * 16 + quad + rr * 8;
                const int b = m >> 5, t = m & 31;
                float2 v = make_float2(acc[mt][nt][rr*2], acc[mt][nt][rr*2+1]);
                *(float2*)(gout + (((size_t)b * HH + h) * TT + t) * HSS + d) = v;
            }
        }
    }
}

// ---------------------------------------------------------------------------
// Kernel 2: attention. one warp per (b,h). Exact fp32 causal softmax.
// Writes g_ot[b*32+d][h*32+t] (head-concat transpose, K-major for K3).
// ---------------------------------------------------------------------------
__global__ void __launch_bounds__(256, 1)
attn_kernel()
{
    extern __shared__ uint32_t smu[];
    float* smf = (float*)smu;
    const int tid = threadIdx.x, warp = tid >> 5, lane = tid & 31;
    const int g = blockIdx.x * 8 + warp;          // g = b*16 + h
    const int t = lane;
    float* ksm = smf + warp * 2304;               // 32 rows, stride 36
    float* vsm = ksm + 1152;

    const float* qb = g_q + (size_t)g * 1024;
    const float* kb = g_k + (size_t)g * 1024;
    const float* vb = g_v + (size_t)g * 1024;

    float q[32];
    #pragma unroll
    for (int j = 0; j < 8; j++) {
        float4 v = *(const float4*)(qb + t * 32 + j * 4);
        q[4*j] = v.x; q[4*j+1] = v.y; q[4*j+2] = v.z; q[4*j+3] = v.w;
        *(float4*)(ksm + t * 36 + j * 4) = *(const float4*)(kb + t * 32 + j * 4);
        *(float4*)(vsm + t * 36 + j * 4) = *(const float4*)(vb + t * 32 + j * 4);
    }
    __syncwarp();

    float r[32];
    #pragma unroll
    for (int s = 0; s < 32; s++) {
        float a = 0.f;
        #pragma unroll
        for (int j = 0; j < 8; j++) {
            float4 kv = *(const float4*)(ksm + s * 36 + j * 4);
            a += q[4*j]*kv.x + q[4*j+1]*kv.y + q[4*j+2]*kv.z + q[4*j+3]*kv.w;
        }
        r[s] = (s <= t) ? a * 0.17677669529663689f : -3.0e38f;
    }
    float mx = r[0];
    #pragma unroll
    for (int s = 1; s < 32; s++) mx = fmaxf(mx, r[s]);
    float sum = 0.f;
    #pragma unroll
    for (int s = 0; s < 32; s++) { r[s] = __expf(r[s] - mx); sum += r[s]; }
    const float inv = 1.f / sum;

    float o[32];
    #pragma unroll
    for (int j = 0; j < 32; j++) o[j] = 0.f;
    #pragma unroll
    for (int s = 0; s < 32; s++) {
        float w = r[s];
        #pragma unroll
        for (int j = 0; j < 8; j++) {
            float4 vv = *(const float4*)(vsm + s * 36 + j * 4);
            o[4*j] += w*vv.x; o[4*j+1] += w*vv.y; o[4*j+2] += w*vv.z; o[4*j+3] += w*vv.w;
        }
    }
    __syncwarp();   // done reading ksm -> reuse as transpose buffer
    #pragma unroll
    for (int j = 0; j < 32; j++) ksm[t * 33 + j] = o[j] * inv;
    __syncwarp();

    const int b = g >> 4, h = g & 15;
    float* dst = g_ot + ((size_t)b * 32 + lane) * EE + h * 32;   // lane = d
    #pragma unroll
    for (int tt = 0; tt < 32; tt += 4) {
        float4 v;
        v.x = ksm[(tt + 0) * 33 + lane];
        v.y = ksm[(tt + 1) * 33 + lane];
        v.z = ksm[(tt + 2) * 33 + lane];
        v.w = ksm[(tt + 3) * 33 + lane];
        *(float4*)(dst + tt) = v;
    }
}

// ---------------------------------------------------------------------------
// Kernel 3: output projection + bias. grid(4, 1024): x = N tile, y = M tile.
// out[m][n] = sum_c g_ot[m][c] * Wp[n][c] + bp[n]
// ---------------------------------------------------------------------------
__global__ void __launch_bounds__(256, 1)
gemm_proj_kernel(const float* __restrict__ Wp, const float* __restrict__ bp,
                 float* __restrict__ out)
{
    extern __shared__ uint32_t smu[];
    const int tid = threadIdx.x, warp = tid >> 5, lane = tid & 31;
    const int quad = lane >> 2, tq = lane & 3;
    const int wm = warp & 1, wn = warp >> 1;
    const int n0 = blockIdx.x * 128;
    const int m0 = blockIdx.y * 128;

    float acc[4][4][4];
    #pragma unroll
    for (int i = 0; i < 4; i++)
        #pragma unroll
        for (int j = 0; j < 4; j++)
            #pragma unroll
            for (int k = 0; k < 4; k++) acc[i][j][k] = 0.f;

    gemm_mainloop(g_ot + (size_t)m0 * EE, Wp + (size_t)n0 * EE,
                  smu, tid, wm, wn, quad, tq, acc);

    #pragma unroll
    for (int mt = 0; mt < 4; mt++) {
        #pragma unroll
        for (int nt = 0; nt < 4; nt++) {
            const int n = n0 + wn * 32 + nt * 8 + 2 * tq;
            const float b0 = bp[n], b1 = bp[n + 1];
            #pragma unroll
            for (int rr = 0; rr < 2; rr++) {
                const int m = m0 + wm * 64 + mt * 16 + quad + rr * 8;
                float2 v = make_float2(acc[mt][nt][rr*2] + b0,
                                       acc[mt][nt][rr*2+1] + b1);
                *(float2*)(out + (size_t)m * EE + n) = v;
            }
        }
    }
}

// ---------------------------------------------------------------------------
// Launch
// ---------------------------------------------------------------------------
extern "C" void kernel_launch(void* const* d_in, const int* in_sizes, int n_in,
                              void* d_out, int out_size)
{
    const float* x  = (const float*)d_in[0];
    const float* Wq = (const float*)d_in[1];
    const float* Wk = (const float*)d_in[2];
    const float* Wv = (const float*)d_in[3];
    const float* Wp = (const float*)d_in[4];
    const float* bp = (const float*)d_in[5];
    float* out = (float*)d_out;

    const int smem_attn = 8 * 2304 * 4;   // 73728

    cudaFuncSetAttribute(gemm_qkv_kernel,  cudaFuncAttributeMaxDynamicSharedMemorySize, SMEM_GEMM);
    cudaFuncSetAttribute(gemm_proj_kernel, cudaFuncAttributeMaxDynamicSharedMemorySize, SMEM_GEMM);
    cudaFuncSetAttribute(attn_kernel,      cudaFuncAttributeMaxDynamicSharedMemorySize, smem_attn);

    gemm_qkv_kernel<<<dim3(12, 1024), 256, SMEM_GEMM>>>(x, Wq, Wk, Wv);
    attn_kernel<<<(BB * HH) / 8, 256, smem_attn>>>();
    gemm_proj_kernel<<<dim3(4, 1024), 256, SMEM_GEMM>>>(Wp, bp, out);
}